// round 17
// baseline (speedup 1.0000x reference)
#include <cuda_runtime.h>
#include <cuda_bf16.h>
#include <cstdint>

// ---------------- dims ----------------
#define T_LEN  1024
#define NBG    16       // batch groups (16 batch each)
#define NGG    8        // gate-slice CTAs per group
#define BB     16
#define NTHR   512

// ---------------- smem layout (bytes) ----------------
// W fragment regions: [hi_t01, hi_t23, lo_t01, lo_t23], each [gate4][ks20][lane32][16B]
#define WREG     40960
#define W_OFF    0
#define HX_OFF   (4 * WREG)            // 163840: hx hi [20][32][16B] then lo (+10240)
#define SP_OFF   (HX_OFF + 20480)      // 184320: 4 partial spills, [b16][136 floats]
#define SP_Q     8704
#define SMEM_TOTAL (SP_OFF + 4 * SP_Q)   // 219136

// ---------------- static scratch ----------------
// hx ring in fragment layout: [t][bg]{hi 10240 | lo 10240}; x pre-staged at ks16..19
__device__ char          g_B[(size_t)(T_LEN + 1) * NBG * 20480];
__device__ float         g_Hf[256][256];
__device__ unsigned int  g_tag[NBG * 8 * 16];   // per-producer tags, 64B stride

// ---------------- helpers ----------------
__device__ __forceinline__ unsigned int ld_acq(const unsigned int* p) {
  unsigned int v;
  asm volatile("ld.acquire.gpu.global.u32 %0, [%1];" : "=r"(v) : "l"(p) : "memory");
  return v;
}
__device__ __forceinline__ void red_rel(unsigned int* p) {
  asm volatile("red.release.gpu.global.add.u32 [%0], 1;" :: "l"(p) : "memory");
}
__device__ __forceinline__ float fsig(float x) {
  x = fminf(fmaxf(x, -15.0f), 15.0f);
  return __fdividef(1.0f, 1.0f + __expf(-x));
}
__device__ __forceinline__ float ftanh(float x) {
  x = fminf(fmaxf(x, -15.0f), 15.0f);
  float e = __expf(-2.0f * x);
  return __fdividef(1.0f - e, 1.0f + e);
}
__device__ __forceinline__ void mma16816(float* d, const uint4& a,
                                         uint32_t b0, uint32_t b1) {
  asm volatile(
      "mma.sync.aligned.m16n8k16.row.col.f32.bf16.bf16.f32 "
      "{%0,%1,%2,%3}, {%4,%5,%6,%7}, {%8,%9}, {%0,%1,%2,%3};"
      : "+f"(d[0]), "+f"(d[1]), "+f"(d[2]), "+f"(d[3])
      : "r"(a.x), "r"(a.y), "r"(a.z), "r"(a.w), "r"(b0), "r"(b1));
}
// A-frag offset (batch b, k_in) within one kstep's 512B frag
__device__ __forceinline__ int hx_frag_off(int b, int k_in) {
  int u    = (k_in & 7) >> 1;
  int half = k_in & 1;
  int reg  = ((b >> 3) & 1) + ((k_in >> 3) & 1) * 2;
  return ((b & 7) * 4 + u) * 16 + reg * 4 + half * 2;
}

// ---------------- prep kernels ----------------
__global__ void reset_kernel() {
  if (threadIdx.x < NBG * 8 * 16) g_tag[threadIdx.x] = 0u;
}
// stage x (hi/lo) into ring k-steps 16..19 for all t
__global__ void xprep_kernel(const float* __restrict__ x) {
  int id  = blockIdx.x * 256 + threadIdx.x;      // 16,777,216
  int i   = id & 63;
  int t   = (id >> 6) & 1023;
  int bgl = id >> 16;
  float v = x[(size_t)bgl * (T_LEN * 64) + t * 64 + i];
  __nv_bfloat16 hi = __float2bfloat16(v);
  __nv_bfloat16 lo = __float2bfloat16(v - __bfloat162float(hi));
  int bg = bgl >> 4, b = bgl & 15;
  int ks = 16 + (i >> 4);
  int off = ks * 512 + hx_frag_off(b, i & 15);
  char* base = g_B + ((size_t)t * NBG + bg) * 20480;
  *(__nv_bfloat16*)(base + off)         = hi;
  *(__nv_bfloat16*)(base + 10240 + off) = lo;
}

// ---------------- main persistent kernel ----------------
__global__ void __launch_bounds__(NTHR, 1) lstm_kernel(
    const float* __restrict__ W_ih, const float* __restrict__ W_hh,
    const float* __restrict__ b_ih, const float* __restrict__ b_hh) {
  extern __shared__ char smem[];
  const int tid  = threadIdx.x;
  const int w    = tid >> 5;
  const int lane = tid & 31;
  const int bg   = blockIdx.x >> 3;
  const int gg   = blockIdx.x & 7;
  const int c0   = gg * 32;

  // ---- one-time: W slice -> smem fragment-major (hi/lo, tiles split) ----
  for (int idx = tid; idx < 128 * 320; idx += NTHR) {
    int r = idx / 320, k = idx - r * 320;
    int gate = r >> 5;
    int gr = gate * 256 + c0 + (r & 31);
    float v = (k < 256) ? W_hh[gr * 256 + k] : W_ih[gr * 64 + (k - 256)];
    __nv_bfloat16 hi = __float2bfloat16(v);
    __nv_bfloat16 lo = __float2bfloat16(v - __bfloat162float(hi));
    int ks = k >> 4, ki = k & 15;
    int u = (ki & 7) >> 1, half = ki & 1, rh = (ki >> 3) & 1;
    int j = (r >> 3) & 3;
    int off = gate * 10240 + ks * 512 + ((r & 7) * 4 + u) * 16 +
              (j & 1) * 8 + rh * 4 + half * 2;
    int regidx = j >> 1;
    *(__nv_bfloat16*)(smem + W_OFF + regidx * WREG + off)       = hi;
    *(__nv_bfloat16*)(smem + W_OFF + (2 + regidx) * WREG + off) = lo;
  }

  // zero h region of hx (both planes, ks 0..15)
  for (int i = tid; i < 1024; i += NTHR) {
    int off = (i >> 9) * 10240 + (i & 511) * 16;
    *(uint4*)(smem + HX_OFF + off) = make_uint4(0, 0, 0, 0);
  }
  // x stage: tid<256 handle one 16B chunk (4KB x region, both planes); preload x(0)
  const int xoff = (tid >> 7) * 10240 + 8192 + (tid & 127) * 16;
  if (tid < 256) {
    const char* src = g_B + (size_t)bg * 20480;
    *(uint4*)(smem + HX_OFF + xoff) = __ldcg((const uint4*)(src + xoff));
  }

  // ---- MMA mapping: ns = gate slice, kh = contiguous k-half, sub = quarter ----
  const int ns  = w & 3;
  const int kh  = (w >> 2) & 1;
  const int sub = w >> 3;
  const int ks0 = kh * 8 + sub * 4;        // 4 h-ksteps from here
  const int ksx = 16 + kh * 2 + sub;       // this warp's x-kstep
  const char* pAh = smem + HX_OFF + lane * 16;   // + ks*512 (+10240 for lo)
  const char* pBb = smem + W_OFF + ns * 10240 + lane * 16;

  // per-half h copy-in: 2 x 16B chunks per thread over half's 8KB (8 ks x 2 planes)
  const int hrank = sub * 128 + ns * 32 + lane;   // 0..255 within this half
  int hoffH[2];
#pragma unroll
  for (int i = 0; i < 2; i++) {
    int m = hrank + i * 256;                 // 0..511
    hoffH[i] = (m >> 8) * 10240 + (kh * 8 + ((m >> 5) & 7)) * 512 + (m & 31) * 16;
  }
  // tags: this half waits on producers kh*4 + (lane&3); own tag = gg
  const unsigned int* wtag  = g_tag + bg * 128 + (kh * 4 + (lane & 3)) * 16;
  unsigned int*       mytag = g_tag + bg * 128 + gg * 16;

  // ---- epilogue mapping: one (b, hc) per thread ----
  const int eb  = w;            // 0..15
  const int ehc = lane;         // 0..31
  float bias[4];
#pragma unroll
  for (int g = 0; g < 4; g++)
    bias[g] = b_ih[g * 256 + c0 + ehc] + b_hh[g * 256 + c0 + ehc];
  float cs = 0.f;
  const int eks  = gg * 2 + (ehc >> 4);
  const int ekin = ehc & 15;
  const int puboff = eks * 512 + hx_frag_off(eb, ekin);

  __syncthreads();

  for (int t = 0; t < T_LEN; t++) {
    const char* ringT  = g_B + ((size_t)t * NBG + bg) * 20480;
    char*       ringT1 = g_B + ((size_t)(t + 1) * NBG + bg) * 20480;

    // ---- prefetch x(t+1) (pre-staged, h-independent) ----
    uint4 xv;
    if (tid < 256) xv = __ldcg((const uint4*)(ringT1 + xoff));

    // ---- per-half wait on own 4 producers; then issue h LDGs ----
    uint4 hv0, hv1;
    if (t) {
      unsigned int target = (unsigned int)t;
      while (true) {
        unsigned int v = ld_acq(wtag);
        if (__all_sync(0xFFFFFFFFu, v >= target)) break;
      }
      hv0 = __ldcg((const uint4*)(ringT + hoffH[0]));
      hv1 = __ldcg((const uint4*)(ringT + hoffH[1]));
    }

    float acc[16];
#pragma unroll
    for (int i = 0; i < 16; i++) acc[i] = 0.f;

    // ---- x-kstep MMAs while h LDGs fly ----
    {
      int ks = ksx;
      uint4 aH  = *(const uint4*)(pAh + ks * 512);
      uint4 aL  = *(const uint4*)(pAh + 10240 + ks * 512);
      uint4 bh0 = *(const uint4*)(pBb + ks * 512);
      uint4 bh1 = *(const uint4*)(pBb + WREG + ks * 512);
      uint4 bl0 = *(const uint4*)(pBb + 2 * WREG + ks * 512);
      uint4 bl1 = *(const uint4*)(pBb + 3 * WREG + ks * 512);
      mma16816(acc + 0,  aH, bh0.x, bh0.y);
      mma16816(acc + 0,  aH, bl0.x, bl0.y);
      mma16816(acc + 0,  aL, bh0.x, bh0.y);
      mma16816(acc + 4,  aH, bh0.z, bh0.w);
      mma16816(acc + 4,  aH, bl0.z, bl0.w);
      mma16816(acc + 4,  aL, bh0.z, bh0.w);
      mma16816(acc + 8,  aH, bh1.x, bh1.y);
      mma16816(acc + 8,  aH, bl1.x, bl1.y);
      mma16816(acc + 8,  aL, bh1.x, bh1.y);
      mma16816(acc + 12, aH, bh1.z, bh1.w);
      mma16816(acc + 12, aH, bl1.z, bl1.w);
      mma16816(acc + 12, aL, bh1.z, bh1.w);
    }

    // ---- land this half's h frags; half-barrier (256 threads) ----
    if (t) {
      *(uint4*)(smem + HX_OFF + hoffH[0]) = hv0;
      *(uint4*)(smem + HX_OFF + hoffH[1]) = hv1;
      asm volatile("bar.sync %0, 256;" :: "r"(1 + kh) : "memory");
    }

    // ---- h-part MMAs: 4 contiguous ksteps ----
#pragma unroll
    for (int j = 0; j < 4; j++) {
      int ks = ks0 + j;
      uint4 aH  = *(const uint4*)(pAh + ks * 512);
      uint4 aL  = *(const uint4*)(pAh + 10240 + ks * 512);
      uint4 bh0 = *(const uint4*)(pBb + ks * 512);
      uint4 bh1 = *(const uint4*)(pBb + WREG + ks * 512);
      uint4 bl0 = *(const uint4*)(pBb + 2 * WREG + ks * 512);
      uint4 bl1 = *(const uint4*)(pBb + 3 * WREG + ks * 512);
      mma16816(acc + 0,  aH, bh0.x, bh0.y);
      mma16816(acc + 0,  aH, bl0.x, bl0.y);
      mma16816(acc + 0,  aL, bh0.x, bh0.y);
      mma16816(acc + 4,  aH, bh0.z, bh0.w);
      mma16816(acc + 4,  aH, bl0.z, bl0.w);
      mma16816(acc + 4,  aL, bh0.z, bh0.w);
      mma16816(acc + 8,  aH, bh1.x, bh1.y);
      mma16816(acc + 8,  aH, bl1.x, bl1.y);
      mma16816(acc + 8,  aL, bh1.x, bh1.y);
      mma16816(acc + 12, aH, bh1.z, bh1.w);
      mma16816(acc + 12, aH, bl1.z, bl1.w);
      mma16816(acc + 12, aL, bh1.z, bh1.w);
    }

    // ---- spill partials: [kh*2+sub][b16][136] ----
    {
      float* sp = (float*)(smem + SP_OFF) + (kh * 2 + sub) * 2176;
      int q = lane >> 2, cp2 = (lane & 3) * 2;
#pragma unroll
      for (int tl = 0; tl < 4; tl++) {
        int r = ns * 32 + tl * 8 + cp2;
        *(float2*)(sp + q * 136 + r)       = make_float2(acc[tl * 4], acc[tl * 4 + 1]);
        *(float2*)(sp + (q + 8) * 136 + r) = make_float2(acc[tl * 4 + 2], acc[tl * 4 + 3]);
      }
    }
    __syncthreads();

    // ---- epilogue: combine 4 partials, activations, publish h(t+1) ----
    {
      const float* sp = (const float*)(smem + SP_OFF);
      float gsum[4];
#pragma unroll
      for (int g = 0; g < 4; g++) {
        float s = bias[g];
#pragma unroll
        for (int q = 0; q < 4; q++)
          s += sp[q * 2176 + eb * 136 + g * 32 + ehc];
        gsum[g] = s;
      }
      float iv = fsig(gsum[0]), fv = fsig(gsum[1]);
      float cv = ftanh(gsum[2]), ov = fsig(gsum[3]);
      float cn = fv * cs + iv * cv;
      cs = cn;
      float hvv = ov * ftanh(cn);
      __nv_bfloat16 hi = __float2bfloat16(hvv);
      __nv_bfloat16 lo = __float2bfloat16(hvv - __bfloat162float(hi));
      *(__nv_bfloat16*)(ringT1 + puboff)         = hi;
      *(__nv_bfloat16*)(ringT1 + 10240 + puboff) = lo;
      if (t == T_LEN - 1) g_Hf[bg * BB + eb][c0 + ehc] = hvv;
      // stage x(t+1) (x(t) fully consumed above)
      if (tid < 256) *(uint4*)(smem + HX_OFF + xoff) = xv;
    }
    __syncthreads();
    if (tid == 0) red_rel(mytag);
  }
}

// ---------------- fc ----------------
__global__ void fc_kernel(const float* __restrict__ fc_w,
                          const float* __restrict__ fc_b,
                          float* __restrict__ out) {
  int b = blockIdx.x;
  float s = g_Hf[b][threadIdx.x] * fc_w[threadIdx.x];
#pragma unroll
  for (int o = 16; o; o >>= 1) s += __shfl_xor_sync(0xFFFFFFFFu, s, o);
  __shared__ float ps[8];
  if ((threadIdx.x & 31) == 0) ps[threadIdx.x >> 5] = s;
  __syncthreads();
  if (threadIdx.x == 0) {
    float tt = 0.f;
#pragma unroll
    for (int i = 0; i < 8; i++) tt += ps[i];
    out[b] = tt + fc_b[0];
  }
}

// ---------------- launch ----------------
extern "C" void kernel_launch(void* const* d_in, const int* in_sizes, int n_in,
                              void* d_out, int out_size) {
  const float* x    = (const float*)d_in[0];
  const float* W_ih = (const float*)d_in[1];
  const float* W_hh = (const float*)d_in[2];
  const float* b_ih = (const float*)d_in[3];
  const float* b_hh = (const float*)d_in[4];
  const float* fc_w = (const float*)d_in[5];
  const float* fc_b = (const float*)d_in[6];
  float* out = (float*)d_out;

  static bool init = false;
  if (!init) {
    cudaFuncSetAttribute(lstm_kernel,
                         cudaFuncAttributeMaxDynamicSharedMemorySize, SMEM_TOTAL);
    init = true;
  }

  reset_kernel<<<2, 1024>>>();
  xprep_kernel<<<65536, 256>>>(x);
  lstm_kernel<<<NBG * NGG, NTHR, SMEM_TOTAL>>>(W_ih, W_hh, b_ih, b_hh);
  fc_kernel<<<256, 256>>>(fc_w, fc_b, out);
}